// round 1
// baseline (speedup 1.0000x reference)
#include <cuda_runtime.h>

// Problem constants (fixed shapes for this problem)
#define N_MAX 100000
#define E_MAX 800000
#define HC    100     // heads*channels
#define DD    100     // in dim
#define TT    100     // time dim
#define MMsz  172     // msg dim
#define EDIM  272     // TT + MMsz

typedef unsigned long long ull;

// Scratch: node projections [N][400] = q|k|v|skip, accumulators, denominators
__device__ float g_nproj[(size_t)N_MAX * 400];
__device__ float g_acc[(size_t)N_MAX * HC];
__device__ float g_denom[(size_t)N_MAX * 2];

__device__ __forceinline__ void ffma2(ull &acc, ull a, ull b) {
    asm("fma.rn.f32x2 %0, %1, %2, %0;" : "+l"(acc) : "l"(a), "l"(b));
}
__device__ __forceinline__ ull pack2(float x, float y) {
    ull r; asm("mov.b64 %0, {%1, %2};" : "=l"(r) : "f"(x), "f"(y)); return r;
}
__device__ __forceinline__ float2 unpack2(ull v) {
    float2 f; asm("mov.b64 {%0, %1}, %2;" : "=f"(f.x), "=f"(f.y) : "l"(v)); return f;
}

// ---------------------------------------------------------------------------
// Kernel 0: zero accumulators
// ---------------------------------------------------------------------------
__global__ void k_zero(int n) {
    int tot = n * (HC + 2);
    int accN = n * HC;
    for (int i = blockIdx.x * blockDim.x + threadIdx.x; i < tot;
         i += gridDim.x * blockDim.x) {
        if (i < accN) g_acc[i] = 0.0f;
        else          g_denom[i - accN] = 0.0f;
    }
}

// ---------------------------------------------------------------------------
// Kernel 1: node projections  nproj[n][0:400] = x[n] @ [Wq|Wk|Wv|Ws] + [bq|bk|bv|bs]
// Warp handles 4 nodes; lane handles col-quads {32r+lane : r<4}. f32x2 FMAs.
// smem: weights [k][400] (160KB) + bias (1.6KB) + dup'd x rows per warp (38.4KB)
// ---------------------------------------------------------------------------
__global__ void __launch_bounds__(384, 1) k_nproj(
    const float* __restrict__ x,
    const float* __restrict__ Wq, const float* __restrict__ bq,
    const float* __restrict__ Wk, const float* __restrict__ bk,
    const float* __restrict__ Wv, const float* __restrict__ bv,
    const float* __restrict__ Ws, const float* __restrict__ bs,
    int n)
{
    extern __shared__ float sm[];
    float* wsm  = sm;            // 40000 floats: wsm[k*400 + c]
    float* bsm  = sm + 40000;    // 400 floats
    float* asmm = sm + 40400;    // 12 warps * 4 nodes * 200 floats (float2 dup)

    int tid = threadIdx.x;
    for (int i = tid; i < 40000; i += 384) {
        int k = i / 400, c = i % 400;
        float v;
        if      (c < 100) v = Wq[k * 100 + c];
        else if (c < 200) v = Wk[k * 100 + c - 100];
        else if (c < 300) v = Wv[k * 100 + c - 200];
        else              v = Ws[k * 100 + c - 300];
        wsm[i] = v;
    }
    for (int i = tid; i < 400; i += 384) {
        bsm[i] = (i < 100) ? bq[i] : (i < 200) ? bk[i - 100]
               : (i < 300) ? bv[i - 200] : bs[i - 300];
    }
    __syncthreads();

    int warp = tid >> 5, lane = tid & 31;
    int gwarp = blockIdx.x * 12 + warp;
    int nwarps = gridDim.x * 12;
    float* aw = asmm + warp * 800;   // 4 nodes * 100 float2
    float2* ap = (float2*)aw;

    int nblocks = (n + 3) >> 2;
    for (int blk = gwarp; blk < nblocks; blk += nwarps) {
        int nbase = blk * 4;
        // fill dup'd x rows
        #pragma unroll
        for (int e = 0; e < 4; e++) {
            int nd = nbase + e;
            const float* xr = x + (size_t)((nd < n) ? nd : (n - 1)) * 100;
            for (int j = lane; j < 100; j += 32) {
                float v = xr[j];
                ap[e * 100 + j] = make_float2(v, v);
            }
        }
        __syncwarp();

        // init acc with bias
        ull acc[4][4][2];
        #pragma unroll
        for (int r = 0; r < 4; r++) {
            int q = r * 32 + lane;
            int qc = (q < 100) ? q : 99;
            float4 b4 = ((const float4*)bsm)[qc];
            ull lo = pack2(b4.x, b4.y), hi = pack2(b4.z, b4.w);
            #pragma unroll
            for (int e = 0; e < 4; e++) { acc[e][r][0] = lo; acc[e][r][1] = hi; }
        }

        #pragma unroll 2
        for (int k = 0; k < 100; k += 2) {
            ulonglong2 a2[4];
            #pragma unroll
            for (int e = 0; e < 4; e++)
                a2[e] = *(const ulonglong2*)(aw + e * 200 + k * 2);
            #pragma unroll
            for (int r = 0; r < 4; r++) {
                int q = r * 32 + lane;
                int qc = (q < 100) ? q : 99;
                ulonglong2 w0 = *(const ulonglong2*)(wsm + k * 400 + qc * 4);
                ulonglong2 w1 = *(const ulonglong2*)(wsm + (k + 1) * 400 + qc * 4);
                #pragma unroll
                for (int e = 0; e < 4; e++) {
                    ffma2(acc[e][r][0], a2[e].x, w0.x);
                    ffma2(acc[e][r][1], a2[e].x, w0.y);
                    ffma2(acc[e][r][0], a2[e].y, w1.x);
                    ffma2(acc[e][r][1], a2[e].y, w1.y);
                }
            }
        }

        #pragma unroll
        for (int e = 0; e < 4; e++) {
            int nd = nbase + e;
            if (nd >= n) continue;
            #pragma unroll
            for (int r = 0; r < 4; r++) {
                int q = r * 32 + lane;
                if (q < 100) {
                    float2 lo = unpack2(acc[e][r][0]);
                    float2 hi = unpack2(acc[e][r][1]);
                    *(float4*)(g_nproj + (size_t)nd * 400 + q * 4) =
                        make_float4(lo.x, lo.y, hi.x, hi.y);
                }
            }
        }
        __syncwarp();
    }
}

// ---------------------------------------------------------------------------
// Kernel 2: per-edge. Warp handles 4 edges. Lane l (<25) owns channels 4l..4l+3.
//   a = [cos(rel*Wt+bt) (100) | msg (172)], stored dup'd as float2{v,v}
//   e_vec = a @ We   (f32x2 FMAs, We in smem)
//   alpha_h = dot(q[dst], k[src]+e) * scale ; ex = exp(alpha)
//   atomic: denom[dst][h] += ex ; acc[dst][c] += ex * (v[src][c] + e[c])
// ---------------------------------------------------------------------------
__global__ void __launch_bounds__(384, 1) k_edge(
    const float* __restrict__ lu, const float* __restrict__ t,
    const float* __restrict__ msg,
    const float* __restrict__ Wt, const float* __restrict__ bt,
    const float* __restrict__ We, const int* __restrict__ ei,
    int n, int ne)
{
    extern __shared__ float sm[];
    float* wsm  = sm;            // 27200 floats: wsm[j*100 + c] = We[j][c]
    float* asmm = sm + 27200;    // 12 warps * 4 edges * 544 floats

    int tid = threadIdx.x;
    for (int i = tid; i < 27200; i += 384) wsm[i] = We[i];
    __syncthreads();

    int warp = tid >> 5, lane = tid & 31;
    int gwarp = blockIdx.x * 12 + warp;
    int nwarps = gridDim.x * 12;
    float* aw = asmm + warp * (4 * 544);
    const float SCALE = 0.14142135623730951f;   // 1/sqrt(50)
    int lq = (lane < 25) ? lane : 24;

    int nblk = (ne + 3) >> 2;
    for (int blk = gwarp; blk < nblk; blk += nwarps) {
        int ebase = blk * 4;
        int src4[4], dst4[4], val4[4];
        __syncwarp();
        #pragma unroll
        for (int e = 0; e < 4; e++) {
            int eid = ebase + e;
            int valid = (eid < ne);
            int eids = valid ? eid : 0;
            int s = ei[eids];
            int d = ei[ne + eids];
            src4[e] = s; dst4[e] = d; val4[e] = valid;
            float rel = lu[s] - t[eids];
            float2* ae = (float2*)(aw + e * 544);
            for (int j = lane; j < 100; j += 32) {
                float cv = __cosf(fmaf(rel, Wt[j], bt[j]));
                ae[j] = make_float2(cv, cv);
            }
            const float* mrow = msg + (size_t)eids * 172;
            for (int j = lane; j < 172; j += 32) {
                float mv = valid ? mrow[j] : 0.0f;
                ae[100 + j] = make_float2(mv, mv);
            }
        }
        __syncwarp();

        ull acc[4][2];
        #pragma unroll
        for (int e = 0; e < 4; e++) { acc[e][0] = 0ull; acc[e][1] = 0ull; }

        #pragma unroll 2
        for (int j = 0; j < 272; j += 2) {
            ulonglong2 w0 = *(const ulonglong2*)(wsm + j * 100 + lq * 4);
            ulonglong2 w1 = *(const ulonglong2*)(wsm + (j + 1) * 100 + lq * 4);
            #pragma unroll
            for (int e = 0; e < 4; e++) {
                ulonglong2 a2 = *(const ulonglong2*)(aw + e * 544 + j * 2);
                ffma2(acc[e][0], a2.x, w0.x);
                ffma2(acc[e][1], a2.x, w0.y);
                ffma2(acc[e][0], a2.y, w1.x);
                ffma2(acc[e][1], a2.y, w1.y);
            }
        }

        #pragma unroll
        for (int e = 0; e < 4; e++) {
            if (!val4[e]) continue;  // uniform across warp
            int s = src4[e], d = dst4[e];
            float2 e0 = unpack2(acc[e][0]);   // ch 4l, 4l+1
            float2 e1 = unpack2(acc[e][1]);   // ch 4l+2, 4l+3
            float d0 = 0.0f, d1 = 0.0f;
            float4 qv, kv, vv;
            if (lane < 25) {
                qv = *(const float4*)(g_nproj + (size_t)d * 400 + lane * 4);
                kv = *(const float4*)(g_nproj + (size_t)s * 400 + 100 + lane * 4);
                vv = *(const float4*)(g_nproj + (size_t)s * 400 + 200 + lane * 4);
                d0 = qv.x * (kv.x + e0.x) + qv.y * (kv.y + e0.y);
                d1 = qv.z * (kv.z + e1.x) + qv.w * (kv.w + e1.y);
            }
            // head of pair (4l,4l+1): head0 iff lane<13 ; pair (4l+2,4l+3): head0 iff lane<12
            float p0 = ((lane < 13) ? d0 : 0.0f) + ((lane < 12) ? d1 : 0.0f);
            float p1 = ((lane < 13) ? 0.0f : d0) + ((lane < 12) ? 0.0f : d1);
            #pragma unroll
            for (int o = 16; o > 0; o >>= 1) {
                p0 += __shfl_xor_sync(0xffffffff, p0, o);
                p1 += __shfl_xor_sync(0xffffffff, p1, o);
            }
            float ex0 = __expf(p0 * SCALE);
            float ex1 = __expf(p1 * SCALE);
            if (lane == 0) {
                atomicAdd(&g_denom[(size_t)d * 2 + 0], ex0);
                atomicAdd(&g_denom[(size_t)d * 2 + 1], ex1);
            }
            if (lane < 25) {
                float w0 = (lane < 13) ? ex0 : ex1;
                float w1 = (lane < 12) ? ex0 : ex1;
                float* apo = g_acc + (size_t)d * 100 + lane * 4;
                atomicAdd(apo + 0, w0 * (vv.x + e0.x));
                atomicAdd(apo + 1, w0 * (vv.y + e0.y));
                atomicAdd(apo + 2, w1 * (vv.z + e1.x));
                atomicAdd(apo + 3, w1 * (vv.w + e1.y));
            }
        }
    }
}

// ---------------------------------------------------------------------------
// Kernel 3: finalize  out = acc/denom (0 if no edges) + skip
// ---------------------------------------------------------------------------
__global__ void k_final(float* __restrict__ out, int n) {
    int tot = n * HC;
    for (int i = blockIdx.x * blockDim.x + threadIdx.x; i < tot;
         i += gridDim.x * blockDim.x) {
        int nd = i / 100, c = i % 100;
        float dnm = g_denom[(size_t)nd * 2 + (c >= 50)];
        float a = (dnm > 0.0f) ? (g_acc[i] / dnm) : 0.0f;
        out[i] = a + g_nproj[(size_t)nd * 400 + 300 + c];
    }
}

// ---------------------------------------------------------------------------
extern "C" void kernel_launch(void* const* d_in, const int* in_sizes, int n_in,
                              void* d_out, int out_size) {
    const float* x   = (const float*)d_in[0];
    const float* lu  = (const float*)d_in[1];
    const float* t   = (const float*)d_in[2];
    const float* msg = (const float*)d_in[3];
    const float* Wt  = (const float*)d_in[4];
    const float* bt  = (const float*)d_in[5];
    const float* Wq  = (const float*)d_in[6];
    const float* bq  = (const float*)d_in[7];
    const float* Wk  = (const float*)d_in[8];
    const float* bk  = (const float*)d_in[9];
    const float* Wv  = (const float*)d_in[10];
    const float* bv  = (const float*)d_in[11];
    const float* We  = (const float*)d_in[12];
    const float* Ws  = (const float*)d_in[13];
    const float* bs  = (const float*)d_in[14];
    const int*   ei  = (const int*)d_in[15];

    int n  = in_sizes[1];   // N from last_update
    int ne = in_sizes[2];   // E from t
    float* out = (float*)d_out;

    int dev = 0;
    cudaGetDevice(&dev);
    int nsm = 148;
    cudaDeviceGetAttribute(&nsm, cudaDevAttrMultiProcessorCount, dev);

    size_t smem1 = (size_t)(40000 + 400 + 9600) * 4;     // 200000 B
    size_t smem2 = (size_t)(27200 + 12 * 4 * 544) * 4;   // 213248 B
    cudaFuncSetAttribute(k_nproj, cudaFuncAttributeMaxDynamicSharedMemorySize, (int)smem1);
    cudaFuncSetAttribute(k_edge,  cudaFuncAttributeMaxDynamicSharedMemorySize, (int)smem2);

    k_zero<<<4096, 256>>>(n);
    k_nproj<<<nsm, 384, smem1>>>(x, Wq, bq, Wk, bk, Wv, bv, Ws, bs, n);
    k_edge<<<nsm, 384, smem2>>>(lu, t, msg, Wt, bt, We, ei, n, ne);
    k_final<<<4096, 256>>>(out, n);
}

// round 2
// speedup vs baseline: 1.5489x; 1.5489x over previous
#include <cuda_runtime.h>

#define HC 100
typedef unsigned long long ull;

__device__ float g_nproj[(size_t)100000 * 400];
__device__ float g_acc[(size_t)100000 * HC];
__device__ float g_denom[(size_t)100000 * 2];

__device__ __forceinline__ void ffma2(ull &acc, ull a, ull b) {
    asm("fma.rn.f32x2 %0, %1, %2, %0;" : "+l"(acc) : "l"(a), "l"(b));
}
__device__ __forceinline__ ull pack2(float x, float y) {
    ull r; asm("mov.b64 %0, {%1, %2};" : "=l"(r) : "f"(x), "f"(y)); return r;
}
__device__ __forceinline__ float2 unpack2(ull v) {
    float2 f; asm("mov.b64 {%0, %1}, %2;" : "=f"(f.x), "=f"(f.y) : "l"(v)); return f;
}
__device__ __forceinline__ void red2(float* p, float a, float b) {
    asm volatile("red.global.add.v2.f32 [%0], {%1, %2};" :: "l"(p), "f"(a), "f"(b) : "memory");
}
__device__ __forceinline__ void red4(float* p, float a, float b, float c, float d) {
    asm volatile("red.global.add.v4.f32 [%0], {%1, %2, %3, %4};"
                 :: "l"(p), "f"(a), "f"(b), "f"(c), "f"(d) : "memory");
}
__device__ __forceinline__ void prefetchL2(const void* p) {
    asm volatile("prefetch.global.L2 [%0];" :: "l"(p));
}

// ---------------------------------------------------------------------------
__global__ void k_zero(int n) {
    int na = n * 25;              // float4 count of g_acc
    int tot = na + n;             // + float2 count of g_denom
    float4 z4 = make_float4(0.f, 0.f, 0.f, 0.f);
    for (int i = blockIdx.x * blockDim.x + threadIdx.x; i < tot;
         i += gridDim.x * blockDim.x) {
        if (i < na) ((float4*)g_acc)[i] = z4;
        else        ((float2*)g_denom)[i - na] = make_float2(0.f, 0.f);
    }
}

// ---------------------------------------------------------------------------
// Node projections: warp = 4 nodes, lane<25 owns channel quad 4*lane in each of
// the 4 output groups (q|k|v|s). Weights in smem [k][400]; acts staged undup.
// ---------------------------------------------------------------------------
__global__ void __launch_bounds__(384, 1) k_nproj(
    const float* __restrict__ x,
    const float* __restrict__ Wq, const float* __restrict__ bq,
    const float* __restrict__ Wk, const float* __restrict__ bk,
    const float* __restrict__ Wv, const float* __restrict__ bv,
    const float* __restrict__ Ws, const float* __restrict__ bs,
    int n)
{
    extern __shared__ float sm[];
    float* wsm  = sm;            // 40000: [k][400]
    float* bsm  = sm + 40000;    // 400
    float* actb = sm + 40400;    // 12 warps * 400 floats

    int tid = threadIdx.x;
    for (int i = tid; i < 40000; i += 384) {
        int k = i / 400, c = i % 400;
        float v;
        if      (c < 100) v = Wq[k * 100 + c];
        else if (c < 200) v = Wk[k * 100 + c - 100];
        else if (c < 300) v = Wv[k * 100 + c - 200];
        else              v = Ws[k * 100 + c - 300];
        wsm[i] = v;
    }
    for (int i = tid; i < 400; i += 384) {
        bsm[i] = (i < 100) ? bq[i] : (i < 200) ? bk[i - 100]
               : (i < 300) ? bv[i - 200] : bs[i - 300];
    }
    __syncthreads();

    int warp = tid >> 5, lane = tid & 31;
    int gwarp = blockIdx.x * 12 + warp;
    int nwarps = gridDim.x * 12;
    float* aw = actb + warp * 400;
    int lq = (lane < 25) ? lane : 24;

    int nblocks = (n + 3) >> 2;
    for (int blk = gwarp; blk < nblocks; blk += nwarps) {
        int nbase = blk * 4;
        __syncwarp();
        #pragma unroll
        for (int e = 0; e < 4; e++) {
            int nd = nbase + e; if (nd >= n) nd = n - 1;
            if (lane < 25)
                ((float4*)(aw + e * 100))[lane] =
                    ((const float4*)(x + (size_t)nd * 100))[lane];
        }
        __syncwarp();

        ull acc[4][4][2];
        #pragma unroll
        for (int g = 0; g < 4; g++) {
            ulonglong2 b2 = *(const ulonglong2*)(bsm + g * 100 + lq * 4);
            #pragma unroll
            for (int e = 0; e < 4; e++) { acc[e][g][0] = b2.x; acc[e][g][1] = b2.y; }
        }

        #pragma unroll 1
        for (int k = 0; k < 100; k += 2) {
            ull ad[4][2];
            #pragma unroll
            for (int e = 0; e < 4; e++) {
                float2 a2 = *(const float2*)(aw + e * 100 + k);
                ad[e][0] = pack2(a2.x, a2.x);
                ad[e][1] = pack2(a2.y, a2.y);
            }
            #pragma unroll
            for (int g = 0; g < 4; g++) {
                ulonglong2 w0 = *(const ulonglong2*)(wsm + k * 400 + g * 100 + lq * 4);
                ulonglong2 w1 = *(const ulonglong2*)(wsm + (k + 1) * 400 + g * 100 + lq * 4);
                #pragma unroll
                for (int e = 0; e < 4; e++) {
                    ffma2(acc[e][g][0], ad[e][0], w0.x);
                    ffma2(acc[e][g][1], ad[e][0], w0.y);
                    ffma2(acc[e][g][0], ad[e][1], w1.x);
                    ffma2(acc[e][g][1], ad[e][1], w1.y);
                }
            }
        }

        #pragma unroll
        for (int e = 0; e < 4; e++) {
            int nd = nbase + e;
            if (nd < n && lane < 25) {
                #pragma unroll
                for (int g = 0; g < 4; g++) {
                    float2 lo = unpack2(acc[e][g][0]);
                    float2 hi = unpack2(acc[e][g][1]);
                    *(float4*)(g_nproj + (size_t)nd * 400 + g * 100 + lq * 4) =
                        make_float4(lo.x, lo.y, hi.x, hi.y);
                }
            }
        }
        __syncwarp();
    }
}

// ---------------------------------------------------------------------------
// Edge kernel: warp = 8 edges. Even/odd-K split: each f32x2 accumulator holds
// {sum over even j, sum over odd j} for ONE channel; activation operand is the
// raw {a_j, a_{j+1}} pair (LDS.64, no duplication); weight operand is the
// pre-interleaved {W[2p][c], W[2p+1][c]} pair from 4 conflict-free arrays.
// ---------------------------------------------------------------------------
__global__ void __launch_bounds__(384, 1) k_edge(
    const float* __restrict__ lu, const float* __restrict__ t,
    const float* __restrict__ msg,
    const float* __restrict__ Wt, const float* __restrict__ bt,
    const float* __restrict__ We, const int* __restrict__ ei,
    int n, int ne)
{
    extern __shared__ float sm[];
    // floats [0,27200): weight pairs; ull view: wsu[s*3400 + p*25 + l]
    // floats [27200,27400): Wt | bt
    // floats [27400, ...): per-warp activations, 8*272 each
    ull* wsu   = (ull*)sm;
    float* wtb = sm + 27200;
    float* actb = sm + 27400;

    int tid = threadIdx.x;
    for (int u = tid; u < 13600; u += 384) {
        int s = u / 3400, rem = u % 3400;
        int p = rem / 25, l = rem % 25;
        int c = 4 * l + s;
        int j0 = 2 * p * 100 + c;
        ((float2*)sm)[u] = make_float2(We[j0], We[j0 + 100]);
    }
    for (int u = tid; u < 100; u += 384) { wtb[u] = Wt[u]; wtb[100 + u] = bt[u]; }
    __syncthreads();

    int warp = tid >> 5, lane = tid & 31;
    int gwarp = blockIdx.x * 12 + warp;
    int nwarps = gridDim.x * 12;
    float* aw = actb + warp * 2176;
    int lq = (lane < 25) ? lane : 24;
    const float SCALE = 0.14142135623730951f;   // 1/sqrt(50)

    int nblk = (ne + 7) >> 3;
    for (int blk = gwarp; blk < nblk; blk += nwarps) {
        int ebase = blk * 8;
        int src8[8], dst8[8];
        unsigned vmask = 0;
        __syncwarp();
        #pragma unroll
        for (int e = 0; e < 8; e++) {
            int eid = ebase + e;
            bool valid = (eid < ne);
            int eids = valid ? eid : 0;
            int s = ei[eids], d = ei[ne + eids];
            src8[e] = s; dst8[e] = d;
            if (valid) vmask |= (1u << e);
            float rel = lu[s] - t[eids];
            float* ae = aw + e * 272;
            #pragma unroll
            for (int r = 0; r < 4; r++) {
                int j = r * 32 + lane;
                if (j < 100) ae[j] = __cosf(fmaf(rel, wtb[j], wtb[100 + j]));
            }
            const float4* m4 = (const float4*)(msg + (size_t)eids * 172);
            float4* a4 = (float4*)(ae + 100);
            a4[lane] = m4[lane];                       // 43 float4 total
            if (lane < 11) a4[32 + lane] = m4[32 + lane];
            if (lane < 25) {
                prefetchL2(g_nproj + (size_t)d * 400 + lane * 4);
                prefetchL2(g_nproj + (size_t)s * 400 + 100 + lane * 4);
                prefetchL2(g_nproj + (size_t)s * 400 + 200 + lane * 4);
            }
        }
        __syncwarp();

        ull acc[8][4];
        #pragma unroll
        for (int e = 0; e < 8; e++) {
            acc[e][0] = 0ull; acc[e][1] = 0ull; acc[e][2] = 0ull; acc[e][3] = 0ull;
        }

        const ull* wp = wsu + lq;
        #pragma unroll 1
        for (int p4 = 0; p4 < 68; p4++) {
            ulonglong2 av[8];
            #pragma unroll
            for (int e = 0; e < 8; e++)
                av[e] = *(const ulonglong2*)(aw + e * 272 + p4 * 4);
            int pi = p4 * 50;
            ull w00 = wp[pi],           w01 = wp[pi + 3400];
            ull w02 = wp[pi + 6800],    w03 = wp[pi + 10200];
            ull w10 = wp[pi + 25],      w11 = wp[pi + 3425];
            ull w12 = wp[pi + 6825],    w13 = wp[pi + 10225];
            #pragma unroll
            for (int e = 0; e < 8; e++) {
                ffma2(acc[e][0], av[e].x, w00);
                ffma2(acc[e][1], av[e].x, w01);
                ffma2(acc[e][2], av[e].x, w02);
                ffma2(acc[e][3], av[e].x, w03);
                ffma2(acc[e][0], av[e].y, w10);
                ffma2(acc[e][1], av[e].y, w11);
                ffma2(acc[e][2], av[e].y, w12);
                ffma2(acc[e][3], av[e].y, w13);
            }
        }

        #pragma unroll 1
        for (int e = 0; e < 8; e++) {
            if (!((vmask >> e) & 1u)) continue;
            int s = src8[e], d = dst8[e];
            float2 f0 = unpack2(acc[e][0]); float ec0 = f0.x + f0.y;  // ch 4l
            float2 f1 = unpack2(acc[e][1]); float ec1 = f1.x + f1.y;  // ch 4l+1
            float2 f2 = unpack2(acc[e][2]); float ec2 = f2.x + f2.y;  // ch 4l+2
            float2 f3 = unpack2(acc[e][3]); float ec3 = f3.x + f3.y;  // ch 4l+3
            float d0 = 0.0f, d1 = 0.0f;
            float4 qv = make_float4(0,0,0,0), kv = qv, vv = qv;
            if (lane < 25) {
                qv = *(const float4*)(g_nproj + (size_t)d * 400 + lane * 4);
                kv = *(const float4*)(g_nproj + (size_t)s * 400 + 100 + lane * 4);
                vv = *(const float4*)(g_nproj + (size_t)s * 400 + 200 + lane * 4);
                d0 = qv.x * (kv.x + ec0) + qv.y * (kv.y + ec1);
                d1 = qv.z * (kv.z + ec2) + qv.w * (kv.w + ec3);
            }
            float p0 = ((lane < 13) ? d0 : 0.0f) + ((lane < 12) ? d1 : 0.0f);
            float p1 = ((lane < 13) ? 0.0f : d0) + ((lane < 12) ? 0.0f : d1);
            #pragma unroll
            for (int o = 16; o > 0; o >>= 1) {
                p0 += __shfl_xor_sync(0xffffffffu, p0, o);
                p1 += __shfl_xor_sync(0xffffffffu, p1, o);
            }
            float ex0 = __expf(p0 * SCALE);
            float ex1 = __expf(p1 * SCALE);
            if (lane == 0) red2(&g_denom[(size_t)d * 2], ex0, ex1);
            if (lane < 25) {
                float w0 = (lane < 13) ? ex0 : ex1;
                float w1 = (lane < 12) ? ex0 : ex1;
                red4(g_acc + (size_t)d * 100 + lane * 4,
                     w0 * (vv.x + ec0), w0 * (vv.y + ec1),
                     w1 * (vv.z + ec2), w1 * (vv.w + ec3));
            }
        }
    }
}

// ---------------------------------------------------------------------------
__global__ void k_final(float* __restrict__ out, int n) {
    int tot = n * 25;   // float4 granularity
    for (int i = blockIdx.x * blockDim.x + threadIdx.x; i < tot;
         i += gridDim.x * blockDim.x) {
        int nd = i / 25, q = i % 25;
        float den0 = g_denom[(size_t)nd * 2 + 0];
        float den1 = g_denom[(size_t)nd * 2 + 1];
        float dxy = (q < 13) ? den0 : den1;   // channels 4q,4q+1
        float dzw = (q < 12) ? den0 : den1;   // channels 4q+2,4q+3
        float rxy = (dxy > 0.0f) ? (1.0f / dxy) : 0.0f;
        float rzw = (dzw > 0.0f) ? (1.0f / dzw) : 0.0f;
        float4 a4 = ((const float4*)g_acc)[i];
        float4 sk = *(const float4*)(g_nproj + (size_t)nd * 400 + 300 + q * 4);
        float4 o;
        o.x = a4.x * rxy + sk.x;
        o.y = a4.y * rxy + sk.y;
        o.z = a4.z * rzw + sk.z;
        o.w = a4.w * rzw + sk.w;
        ((float4*)out)[i] = o;
    }
}

// ---------------------------------------------------------------------------
extern "C" void kernel_launch(void* const* d_in, const int* in_sizes, int n_in,
                              void* d_out, int out_size) {
    const float* x   = (const float*)d_in[0];
    const float* lu  = (const float*)d_in[1];
    const float* t   = (const float*)d_in[2];
    const float* msg = (const float*)d_in[3];
    const float* Wt  = (const float*)d_in[4];
    const float* bt  = (const float*)d_in[5];
    const float* Wq  = (const float*)d_in[6];
    const float* bq  = (const float*)d_in[7];
    const float* Wk  = (const float*)d_in[8];
    const float* bk  = (const float*)d_in[9];
    const float* Wv  = (const float*)d_in[10];
    const float* bv  = (const float*)d_in[11];
    const float* We  = (const float*)d_in[12];
    const float* Ws  = (const float*)d_in[13];
    const float* bs  = (const float*)d_in[14];
    const int*   ei  = (const int*)d_in[15];

    int n  = in_sizes[1];
    int ne = in_sizes[2];
    float* out = (float*)d_out;

    int dev = 0;
    cudaGetDevice(&dev);
    int nsm = 148;
    cudaDeviceGetAttribute(&nsm, cudaDevAttrMultiProcessorCount, dev);

    size_t smem1 = (size_t)(40000 + 400 + 12 * 400) * 4;        // 180800 B
    size_t smem2 = (size_t)(27200 + 200 + 12 * 2176) * 4;       // 214048 B
    cudaFuncSetAttribute(k_nproj, cudaFuncAttributeMaxDynamicSharedMemorySize, (int)smem1);
    cudaFuncSetAttribute(k_edge,  cudaFuncAttributeMaxDynamicSharedMemorySize, (int)smem2);

    k_zero<<<2048, 256>>>(n);
    k_nproj<<<nsm, 384, smem1>>>(x, Wq, bq, Wk, bk, Wv, bv, Ws, bs, n);
    k_edge<<<nsm, 384, smem2>>>(lu, t, msg, Wt, bt, We, ei, n, ne);
    k_final<<<4096, 256>>>(out, n);
}

// round 4
// speedup vs baseline: 1.9085x; 1.2322x over previous
#include <cuda_runtime.h>
#include <cuda_bf16.h>
#include <cstdint>

#define HC 100
typedef unsigned long long ull;

__device__ float g_nproj[(size_t)100000 * 400];
__device__ float g_acc[(size_t)100000 * HC];
__device__ float g_denom[(size_t)100000 * 2];

__device__ __forceinline__ void ffma2(ull &acc, ull a, ull b) {
    asm("fma.rn.f32x2 %0, %1, %2, %0;" : "+l"(acc) : "l"(a), "l"(b));
}
__device__ __forceinline__ ull pack2(float x, float y) {
    ull r; asm("mov.b64 %0, {%1, %2};" : "=l"(r) : "f"(x), "f"(y)); return r;
}
__device__ __forceinline__ float2 unpack2(ull v) {
    float2 f; asm("mov.b64 {%0, %1}, %2;" : "=f"(f.x), "=f"(f.y) : "l"(v)); return f;
}
__device__ __forceinline__ void red2(float* p, float a, float b) {
    asm volatile("red.global.add.v2.f32 [%0], {%1, %2};" :: "l"(p), "f"(a), "f"(b) : "memory");
}
__device__ __forceinline__ void red4(float* p, float a, float b, float c, float d) {
    asm volatile("red.global.add.v4.f32 [%0], {%1, %2, %3, %4};"
                 :: "l"(p), "f"(a), "f"(b), "f"(c), "f"(d) : "memory");
}
__device__ __forceinline__ void prefetchL2(const void* p) {
    asm volatile("prefetch.global.L2 [%0];" :: "l"(p));
}
__device__ __forceinline__ uint32_t smem_u32(const void* p) {
    uint32_t a;
    asm("{ .reg .u64 t; cvta.to.shared.u64 t, %1; cvt.u32.u64 %0, t; }" : "=r"(a) : "l"(p));
    return a;
}
__device__ __forceinline__ void ldsm_x4(uint32_t* r, uint32_t a) {
    asm volatile("ldmatrix.sync.aligned.m8n8.x4.shared.b16 {%0,%1,%2,%3}, [%4];"
                 : "=r"(r[0]), "=r"(r[1]), "=r"(r[2]), "=r"(r[3]) : "r"(a));
}
__device__ __forceinline__ void ldsm_x2(uint32_t* r, uint32_t a) {
    asm volatile("ldmatrix.sync.aligned.m8n8.x2.shared.b16 {%0,%1}, [%2];"
                 : "=r"(r[0]), "=r"(r[1]) : "r"(a));
}
__device__ __forceinline__ void mma16816(float* c, const uint32_t* a, const uint32_t* b) {
    asm volatile("mma.sync.aligned.m16n8k16.row.col.f32.bf16.bf16.f32 "
                 "{%0,%1,%2,%3}, {%4,%5,%6,%7}, {%8,%9}, {%0,%1,%2,%3};"
                 : "+f"(c[0]), "+f"(c[1]), "+f"(c[2]), "+f"(c[3])
                 : "r"(a[0]), "r"(a[1]), "r"(a[2]), "r"(a[3]), "r"(b[0]), "r"(b[1]));
}

// ---------------------------------------------------------------------------
__global__ void k_zero(int n) {
    int na = n * 25;
    int tot = na + n;
    float4 z4 = make_float4(0.f, 0.f, 0.f, 0.f);
    for (int i = blockIdx.x * blockDim.x + threadIdx.x; i < tot;
         i += gridDim.x * blockDim.x) {
        if (i < na) ((float4*)g_acc)[i] = z4;
        else        ((float2*)g_denom)[i - na] = make_float2(0.f, 0.f);
    }
}

// ---------------------------------------------------------------------------
// Node projections (FFMA2 version, proven in R2)
// ---------------------------------------------------------------------------
__global__ void __launch_bounds__(384, 1) k_nproj(
    const float* __restrict__ x,
    const float* __restrict__ Wq, const float* __restrict__ bq,
    const float* __restrict__ Wk, const float* __restrict__ bk,
    const float* __restrict__ Wv, const float* __restrict__ bv,
    const float* __restrict__ Ws, const float* __restrict__ bs,
    int n)
{
    extern __shared__ float sm[];
    float* wsm  = sm;
    float* bsm  = sm + 40000;
    float* actb = sm + 40400;

    int tid = threadIdx.x;
    for (int i = tid; i < 40000; i += 384) {
        int k = i / 400, c = i % 400;
        float v;
        if      (c < 100) v = Wq[k * 100 + c];
        else if (c < 200) v = Wk[k * 100 + c - 100];
        else if (c < 300) v = Wv[k * 100 + c - 200];
        else              v = Ws[k * 100 + c - 300];
        wsm[i] = v;
    }
    for (int i = tid; i < 400; i += 384) {
        bsm[i] = (i < 100) ? bq[i] : (i < 200) ? bk[i - 100]
               : (i < 300) ? bv[i - 200] : bs[i - 300];
    }
    __syncthreads();

    int warp = tid >> 5, lane = tid & 31;
    int gwarp = blockIdx.x * 12 + warp;
    int nwarps = gridDim.x * 12;
    float* aw = actb + warp * 400;
    int lq = (lane < 25) ? lane : 24;

    int nblocks = (n + 3) >> 2;
    for (int blk = gwarp; blk < nblocks; blk += nwarps) {
        int nbase = blk * 4;
        __syncwarp();
        #pragma unroll
        for (int e = 0; e < 4; e++) {
            int nd = nbase + e; if (nd >= n) nd = n - 1;
            if (lane < 25)
                ((float4*)(aw + e * 100))[lane] =
                    ((const float4*)(x + (size_t)nd * 100))[lane];
        }
        __syncwarp();

        ull acc[4][4][2];
        #pragma unroll
        for (int g = 0; g < 4; g++) {
            ulonglong2 b2 = *(const ulonglong2*)(bsm + g * 100 + lq * 4);
            #pragma unroll
            for (int e = 0; e < 4; e++) { acc[e][g][0] = b2.x; acc[e][g][1] = b2.y; }
        }

        #pragma unroll 1
        for (int k = 0; k < 100; k += 2) {
            ull ad[4][2];
            #pragma unroll
            for (int e = 0; e < 4; e++) {
                float2 a2 = *(const float2*)(aw + e * 100 + k);
                ad[e][0] = pack2(a2.x, a2.x);
                ad[e][1] = pack2(a2.y, a2.y);
            }
            #pragma unroll
            for (int g = 0; g < 4; g++) {
                ulonglong2 w0 = *(const ulonglong2*)(wsm + k * 400 + g * 100 + lq * 4);
                ulonglong2 w1 = *(const ulonglong2*)(wsm + (k + 1) * 400 + g * 100 + lq * 4);
                #pragma unroll
                for (int e = 0; e < 4; e++) {
                    ffma2(acc[e][g][0], ad[e][0], w0.x);
                    ffma2(acc[e][g][1], ad[e][0], w0.y);
                    ffma2(acc[e][g][0], ad[e][1], w1.x);
                    ffma2(acc[e][g][1], ad[e][1], w1.y);
                }
            }
        }

        #pragma unroll
        for (int e = 0; e < 4; e++) {
            int nd = nbase + e;
            if (nd < n && lane < 25) {
                #pragma unroll
                for (int g = 0; g < 4; g++) {
                    float2 lo = unpack2(acc[e][g][0]);
                    float2 hi = unpack2(acc[e][g][1]);
                    *(float4*)(g_nproj + (size_t)nd * 400 + g * 100 + lq * 4) =
                        make_float4(lo.x, lo.y, hi.x, hi.y);
                }
            }
        }
        __syncwarp();
    }
}

// ---------------------------------------------------------------------------
// Edge kernel: HMMA (mma.sync m16n8k16 bf16) split GEMM
//   D[128 edges, 104] = A[128,272] * WeT[104,272]
//   A row stride 280 bf16 (560 B), W row stride 280 bf16
// ---------------------------------------------------------------------------
#define SM_WHI 0
#define SM_WLO 58240
#define SM_A   116480
#define SM_SRC 188160
#define SM_DST 188672
#define SM_REL 189184
#define SM_WTB 189696
#define SMEM_EDGE_BYTES 190496

__device__ __forceinline__ void build_tile(
    char* smb, const float* __restrict__ msg, int ebase, int ne, int tid, int lopass)
{
    const float* wtb = (const float*)(smb + SM_WTB);
    const float* rel = (const float*)(smb + SM_REL);
    for (int idx = tid; idx < 4352; idx += 384) {
        int r = idx / 34, g = idx - r * 34;
        int j0 = g * 8;
        int eg = ebase + r; if (eg >= ne) eg = ne - 1;
        float v[8];
        if (j0 + 8 <= 100) {
            float rr = rel[r];
            #pragma unroll
            for (int i = 0; i < 8; i++)
                v[i] = __cosf(fmaf(rr, wtb[j0 + i], wtb[100 + j0 + i]));
        } else if (j0 >= 104) {
            const float4* m4 = (const float4*)(msg + (size_t)eg * 172 + (j0 - 100));
            float4 a = m4[0], b = m4[1];
            v[0] = a.x; v[1] = a.y; v[2] = a.z; v[3] = a.w;
            v[4] = b.x; v[5] = b.y; v[6] = b.z; v[7] = b.w;
        } else {
            float rr = rel[r];
            const float* mrow = msg + (size_t)eg * 172;
            #pragma unroll
            for (int i = 0; i < 8; i++) {
                int j = j0 + i;
                v[i] = (j < 100) ? __cosf(fmaf(rr, wtb[j], wtb[100 + j])) : mrow[j - 100];
            }
        }
        if (lopass) {
            #pragma unroll
            for (int i = 0; i < 8; i++)
                v[i] -= __bfloat162float(__float2bfloat16(v[i]));
        }
        uint32_t p[4];
        #pragma unroll
        for (int i = 0; i < 4; i++) {
            __nv_bfloat162 h;
            h.x = __float2bfloat16(v[2 * i]);
            h.y = __float2bfloat16(v[2 * i + 1]);
            p[i] = *reinterpret_cast<uint32_t*>(&h);
        }
        *(uint4*)(smb + SM_A + r * 560 + j0 * 2) = make_uint4(p[0], p[1], p[2], p[3]);
    }
}

__global__ void __launch_bounds__(384, 1) k_edge(
    const float* __restrict__ lu, const float* __restrict__ t,
    const float* __restrict__ msg,
    const float* __restrict__ Wt, const float* __restrict__ bt,
    const float* __restrict__ We, const int* __restrict__ ei,
    int n, int ne)
{
    extern __shared__ char smb[];
    uint32_t sbase = smem_u32(smb);
    int tid = threadIdx.x;
    int warp = tid >> 5, lane = tid & 31;

    // one-time: W hi/lo [104 n-rows][272 k] bf16, stride 280; cols>=100 zero
    for (int idx = tid; idx < 104 * 272; idx += 384) {
        int c = idx / 272, j = idx - c * 272;
        float w = (c < 100) ? We[j * 100 + c] : 0.0f;
        __nv_bfloat16 h = __float2bfloat16(w);
        float lf = w - __bfloat162float(h);
        *(__nv_bfloat16*)(smb + SM_WHI + c * 560 + j * 2) = h;
        *(__nv_bfloat16*)(smb + SM_WLO + c * 560 + j * 2) = __float2bfloat16(lf);
    }
    {
        float* wtb = (float*)(smb + SM_WTB);
        for (int i = tid; i < 100; i += 384) { wtb[i] = Wt[i]; wtb[100 + i] = bt[i]; }
    }
    __syncthreads();

    int* s_src = (int*)(smb + SM_SRC);
    int* s_dst = (int*)(smb + SM_DST);
    float* s_rel = (float*)(smb + SM_REL);
    float* es = (float*)(smb + SM_A);   // es[104][129] overlays A after MMA
    const float SCALE = 0.14142135623730951f;
    int lq = (lane < 25) ? lane : 24;

    int ntiles = (ne + 127) >> 7;
    for (int tile = blockIdx.x; tile < ntiles; tile += gridDim.x) {
        int ebase = tile << 7;
        __syncthreads();   // prev epilogue done before overwriting es/A/meta

        if (tid < 128) {
            int eg = ebase + tid;
            bool valid = eg < ne;
            int eidx = valid ? eg : 0;
            int s = ei[eidx], d = ei[ne + eidx];
            s_src[tid] = s; s_dst[tid] = d;
            s_rel[tid] = valid ? (lu[s] - t[eidx]) : 0.0f;
            if (valid) {
                const char* qb = (const char*)(g_nproj + (size_t)d * 400);
                const char* kb = (const char*)(g_nproj + (size_t)s * 400 + 100);
                const char* vb = (const char*)(g_nproj + (size_t)s * 400 + 200);
                #pragma unroll
                for (int o = 0; o < 400; o += 128) {
                    prefetchL2(qb + o); prefetchL2(kb + o); prefetchL2(vb + o);
                }
            }
        }
        __syncthreads();

        build_tile(smb, msg, ebase, ne, tid, 0);   // A-hi
        __syncthreads();

        float acc[13][4];
        #pragma unroll
        for (int nf = 0; nf < 13; nf++) {
            acc[nf][0] = 0.f; acc[nf][1] = 0.f; acc[nf][2] = 0.f; acc[nf][3] = 0.f;
        }

        if (warp < 8) {
            int r0 = warp * 16;
            uint32_t abase = sbase + SM_A
                           + (uint32_t)((r0 + (lane & 15)) * 560 + (lane >> 4) * 16);
            uint32_t af[17][4];
            #pragma unroll
            for (int k = 0; k < 17; k++) ldsm_x4(af[k], abase + k * 32);

            // fused pass: Ahi*Whi + Ahi*Wlo
            #pragma unroll
            for (int nf = 0; nf < 13; nf++) {
                uint32_t bhb = sbase + SM_WHI
                    + (uint32_t)((nf * 8 + (lane & 7)) * 560 + (lane >> 3) * 16);
                uint32_t blb = bhb + (SM_WLO - SM_WHI);
                #pragma unroll
                for (int kk = 0; kk < 8; kk++) {
                    uint32_t bh[4], bl[4];
                    ldsm_x4(bh, bhb + kk * 64);
                    ldsm_x4(bl, blb + kk * 64);
                    mma16816(acc[nf], af[2 * kk],     bh);
                    mma16816(acc[nf], af[2 * kk],     bl);
                    mma16816(acc[nf], af[2 * kk + 1], bh + 2);
                    mma16816(acc[nf], af[2 * kk + 1], bl + 2);
                }
                uint32_t b2h[2], b2l[2];
                ldsm_x2(b2h, bhb + 512);
                ldsm_x2(b2l, blb + 512);
                mma16816(acc[nf], af[16], b2h);
                mma16816(acc[nf], af[16], b2l);
            }
        }
        __syncthreads();   // A-hi reads done

        build_tile(smb, msg, ebase, ne, tid, 1);   // A-lo
        __syncthreads();

        if (warp < 8) {
            int r0 = warp * 16;
            uint32_t abase = sbase + SM_A
                           + (uint32_t)((r0 + (lane & 15)) * 560 + (lane >> 4) * 16);
            uint32_t af[17][4];
            #pragma unroll
            for (int k = 0; k < 17; k++) ldsm_x4(af[k], abase + k * 32);

            // pass 3: Alo*Whi
            #pragma unroll
            for (int nf = 0; nf < 13; nf++) {
                uint32_t bhb = sbase + SM_WHI
                    + (uint32_t)((nf * 8 + (lane & 7)) * 560 + (lane >> 3) * 16);
                #pragma unroll
                for (int kk = 0; kk < 8; kk++) {
                    uint32_t bh[4];
                    ldsm_x4(bh, bhb + kk * 64);
                    mma16816(acc[nf], af[2 * kk],     bh);
                    mma16816(acc[nf], af[2 * kk + 1], bh + 2);
                }
                uint32_t b2h[2];
                ldsm_x2(b2h, bhb + 512);
                mma16816(acc[nf], af[16], b2h);
            }
        }
        __syncthreads();   // A-lo reads done before es overwrite

        if (warp < 8) {
            int r0 = warp * 16;
            int rowA = r0 + (lane >> 2);
            #pragma unroll
            for (int nf = 0; nf < 13; nf++) {
                int col = nf * 8 + 2 * (lane & 3);
                es[col * 129 + rowA]           = acc[nf][0];
                es[(col + 1) * 129 + rowA]     = acc[nf][1];
                es[col * 129 + rowA + 8]       = acc[nf][2];
                es[(col + 1) * 129 + rowA + 8] = acc[nf][3];
            }
        }
        __syncthreads();

        // attention epilogue
        #pragma unroll 1
        for (int er = warp; er < 128; er += 12) {
            int eg = ebase + er;
            if (eg >= ne) break;
            int s = s_src[er], d = s_dst[er];
            float ec0 = 0.f, ec1 = 0.f, ec2 = 0.f, ec3 = 0.f, d0 = 0.f, d1 = 0.f;
            float4 qv = make_float4(0,0,0,0), kv = qv, vv = qv;
            if (lane < 25) {
                ec0 = es[(4 * lq + 0) * 129 + er];
                ec1 = es[(4 * lq + 1) * 129 + er];
                ec2 = es[(4 * lq + 2) * 129 + er];
                ec3 = es[(4 * lq + 3) * 129 + er];
                qv = *(const float4*)(g_nproj + (size_t)d * 400 + lq * 4);
                kv = *(const float4*)(g_nproj + (size_t)s * 400 + 100 + lq * 4);
                vv = *(const float4*)(g_nproj + (size_t)s * 400 + 200 + lq * 4);
                d0 = qv.x * (kv.x + ec0) + qv.y * (kv.y + ec1);
                d1 = qv.z * (kv.z + ec2) + qv.w * (kv.w + ec3);
            }
            float p0 = ((lane < 13) ? d0 : 0.0f) + ((lane < 12) ? d1 : 0.0f);
            float p1 = ((lane < 13) ? 0.0f : d0) + ((lane < 12) ? 0.0f : d1);
            #pragma unroll
            for (int o = 16; o > 0; o >>= 1) {
                p0 += __shfl_xor_sync(0xffffffffu, p0, o);
                p1 += __shfl_xor_sync(0xffffffffu, p1, o);
            }
            float ex0 = __expf(p0 * SCALE);
            float ex1 = __expf(p1 * SCALE);
            if (lane == 0) red2(&g_denom[(size_t)d * 2], ex0, ex1);
            if (lane < 25) {
                float w0 = (lane < 13) ? ex0 : ex1;
                float w1 = (lane < 12) ? ex0 : ex1;
                red4(g_acc + (size_t)d * 100 + lq * 4,
                     w0 * (vv.x + ec0), w0 * (vv.y + ec1),
                     w1 * (vv.z + ec2), w1 * (vv.w + ec3));
            }
        }
    }
}

// ---------------------------------------------------------------------------
__global__ void k_final(float* __restrict__ out, int n) {
    int tot = n * 25;
    for (int i = blockIdx.x * blockDim.x + threadIdx.x; i < tot;
         i += gridDim.x * blockDim.x) {
        int nd = i / 25, q = i % 25;
        float den0 = g_denom[(size_t)nd * 2 + 0];
        float den1 = g_denom[(size_t)nd * 2 + 1];
        float dxy = (q < 13) ? den0 : den1;
        float dzw = (q < 12) ? den0 : den1;
        float rxy = (dxy > 0.0f) ? (1.0f / dxy) : 0.0f;
        float rzw = (dzw > 0.0f) ? (1.0f / dzw) : 0.0f;
        float4 a4 = ((const float4*)g_acc)[i];
        float4 sk = *(const float4*)(g_nproj + (size_t)nd * 400 + 300 + q * 4);
        float4 o;
        o.x = a4.x * rxy + sk.x;
        o.y = a4.y * rxy + sk.y;
        o.z = a4.z * rzw + sk.z;
        o.w = a4.w * rzw + sk.w;
        ((float4*)out)[i] = o;
    }
}

// ---------------------------------------------------------------------------
extern "C" void kernel_launch(void* const* d_in, const int* in_sizes, int n_in,
                              void* d_out, int out_size) {
    const float* x   = (const float*)d_in[0];
    const float* lu  = (const float*)d_in[1];
    const float* t   = (const float*)d_in[2];
    const float* msg = (const float*)d_in[3];
    const float* Wt  = (const float*)d_in[4];
    const float* bt  = (const float*)d_in[5];
    const float* Wq  = (const float*)d_in[6];
    const float* bq  = (const float*)d_in[7];
    const float* Wk  = (const float*)d_in[8];
    const float* bk  = (const float*)d_in[9];
    const float* Wv  = (const float*)d_in[10];
    const float* bv  = (const float*)d_in[11];
    const float* We  = (const float*)d_in[12];
    const float* Ws  = (const float*)d_in[13];
    const float* bs  = (const float*)d_in[14];
    const int*   ei  = (const int*)d_in[15];

    int n  = in_sizes[1];
    int ne = in_sizes[2];
    float* out = (float*)d_out;

    int dev = 0;
    cudaGetDevice(&dev);
    int nsm = 148;
    cudaDeviceGetAttribute(&nsm, cudaDevAttrMultiProcessorCount, dev);

    size_t smem1 = (size_t)(40000 + 400 + 12 * 400) * 4;
    cudaFuncSetAttribute(k_nproj, cudaFuncAttributeMaxDynamicSharedMemorySize, (int)smem1);
    cudaFuncSetAttribute(k_edge,  cudaFuncAttributeMaxDynamicSharedMemorySize, SMEM_EDGE_BYTES);

    k_zero<<<2048, 256>>>(n);
    k_nproj<<<nsm, 384, smem1>>>(x, Wq, bq, Wk, bk, Wv, bv, Ws, bs, n);
    k_edge<<<nsm, 384, SMEM_EDGE_BYTES>>>(lu, t, msg, Wt, bt, We, ei, n, ne);
    k_final<<<4096, 256>>>(out, n);
}